// round 13
// baseline (speedup 1.0000x reference)
#include <cuda_runtime.h>

#define DIMC 192
#define HEADS 6
#define HD 32
#define SSH 4
#define NTOK 64
#define NWIN 4096
#define SCALE 0.17677669529663687f   // 32^-0.5
#define QROW 576                      // g_qkv row stride (floats)

typedef unsigned long long u64;

// ---------------- scratch (device globals; no allocations allowed) ----------
__device__ float g_qkv[(size_t)NWIN * NTOK * QROW];   // [win][t][o(576)]
__device__ float g_o  [(size_t)NWIN * DIMC * NTOK];   // [win][c][t]
__device__ float g_wT [DIMC * 576];                   // qkv_w transposed: [k][o]
__device__ float g_pT [DIMC * DIMC];                  // proj_w transposed: [k][o]

// ---------------- f32x2 helpers ----------------------------------------------
__device__ __forceinline__ u64 splat2(float v) {
    u64 r; asm("mov.b64 %0,{%1,%1};" : "=l"(r) : "f"(v)); return r;
}
__device__ __forceinline__ void ffma2(u64& d, u64 a, u64 b) {
    asm("fma.rn.f32x2 %0,%1,%2,%0;" : "+l"(d) : "l"(a), "l"(b));
}
__device__ __forceinline__ float2 unpack2(u64 v) {
    float2 r; asm("mov.b64 {%0,%1},%2;" : "=f"(r.x), "=f"(r.y) : "l"(v)); return r;
}

// ---------------- kernel 0: weight transpose ---------------------------------
__global__ void transpose_weights(const float* __restrict__ qkv_w,
                                  const float* __restrict__ proj_w) {
    int idx = blockIdx.x * 256 + threadIdx.x;
    if (idx < 576 * DIMC) {
        int o = idx / DIMC, k = idx % DIMC;
        g_wT[k * 576 + o] = qkv_w[idx];
    }
    if (idx < DIMC * DIMC) {
        int o = idx / DIMC, k = idx % DIMC;
        g_pT[k * DIMC + o] = proj_w[idx];
    }
}

// ---------------- kernel 1: gather + QKV GEMM ---------------------------------
// One CTA per window. Xs[c][t] in smem; out[t][o] = sum_k Xs[k][t]*wT[k][o] + b.
// warp owns tokens t0..t0+7 (one window row); lane owns 8 outputs per pass.
__global__ __launch_bounds__(256, 2) void qkv_kernel(const float* __restrict__ x,
                                                     const float* __restrict__ qkv_b) {
    __shared__ float Xs[DIMC * NTOK];   // 48KB
    int win = blockIdx.x;
    int b = win >> 10, wy = (win >> 5) & 31, wx = win & 31;
    int tid = threadIdx.x;
    int lane = tid & 31, warp = tid >> 5;

    int y0 = wy * 8 + SSH, x0 = wx * 8 + SSH;
    for (int idx = tid; idx < DIMC * NTOK; idx += 256) {
        int t = idx & 63, c = idx >> 6;
        int yy = (y0 + (t >> 3)) & 255;
        int xx = (x0 + (t & 7)) & 255;
        Xs[idx] = x[(size_t)(b * DIMC + c) * 65536 + yy * 256 + xx];
    }
    __syncthreads();

    int t0 = warp * 8;
    float* gq = g_qkv + (size_t)win * (NTOK * QROW);
    const float* __restrict__ wT = g_wT;

    #pragma unroll 1
    for (int pass = 0; pass < 2; pass++) {
        int ob = pass * 256 + lane * 8;
        u64 acc[4][8];                       // [output-pair][token]
        {
            const u64* bp = (const u64*)&qkv_b[ob];
            #pragma unroll
            for (int op = 0; op < 4; op++) {
                u64 bv = bp[op];
                #pragma unroll
                for (int t = 0; t < 8; t++) acc[op][t] = bv;
            }
        }
        #pragma unroll 4
        for (int k = 0; k < DIMC; k++) {
            float4 a01 = *(const float4*)&Xs[k * 64 + t0];      // broadcast LDS
            float4 a23 = *(const float4*)&Xs[k * 64 + t0 + 4];
            const u64* wr = (const u64*)&wT[k * 576 + ob];      // coalesced LDG
            u64 w0 = wr[0], w1 = wr[1], w2 = wr[2], w3 = wr[3];
            u64 as[8];
            as[0] = splat2(a01.x); as[1] = splat2(a01.y);
            as[2] = splat2(a01.z); as[3] = splat2(a01.w);
            as[4] = splat2(a23.x); as[5] = splat2(a23.y);
            as[6] = splat2(a23.z); as[7] = splat2(a23.w);
            #pragma unroll
            for (int t = 0; t < 8; t++) {
                ffma2(acc[0][t], w0, as[t]);
                ffma2(acc[1][t], w1, as[t]);
                ffma2(acc[2][t], w2, as[t]);
                ffma2(acc[3][t], w3, as[t]);
            }
        }
        #pragma unroll
        for (int t = 0; t < 8; t++) {
            ulonglong2* dst = (ulonglong2*)&gq[(size_t)(t0 + t) * QROW + ob];
            dst[0] = make_ulonglong2(acc[0][t], acc[1][t]);
            dst[1] = make_ulonglong2(acc[2][t], acc[3][t]);
        }
    }
    // tail: outputs 512..575 (2 per lane)
    {
        int ob = 512 + lane * 2;
        u64 acc[8];
        u64 bv = *(const u64*)&qkv_b[ob];
        #pragma unroll
        for (int t = 0; t < 8; t++) acc[t] = bv;
        #pragma unroll 4
        for (int k = 0; k < DIMC; k++) {
            float4 a01 = *(const float4*)&Xs[k * 64 + t0];
            float4 a23 = *(const float4*)&Xs[k * 64 + t0 + 4];
            u64 w = *(const u64*)&wT[k * 576 + ob];
            ffma2(acc[0], w, splat2(a01.x));
            ffma2(acc[1], w, splat2(a01.y));
            ffma2(acc[2], w, splat2(a01.z));
            ffma2(acc[3], w, splat2(a01.w));
            ffma2(acc[4], w, splat2(a23.x));
            ffma2(acc[5], w, splat2(a23.y));
            ffma2(acc[6], w, splat2(a23.z));
            ffma2(acc[7], w, splat2(a23.w));
        }
        #pragma unroll
        for (int t = 0; t < 8; t++)
            *(u64*)&gq[(size_t)(t0 + t) * QROW + ob] = acc[t];
    }
}

// ---------------- kernel 2: windowed attention --------------------------------
// grid (4096, 6), 64 threads; thread i = query row i of (window, head).
__global__ __launch_bounds__(64) void attn_kernel(const float* __restrict__ rpb_table) {
    __shared__ float Ks[NTOK][HD];     // token-major rows (128B)
    __shared__ float Vs[NTOK][HD];
    __shared__ float rpbs[225];        // this head's bias slice
    __shared__ int   regsh[NTOK];

    int win = blockIdx.x, h = blockIdx.y;
    int wy = (win >> 5) & 31, wx = win & 31;
    int i = threadIdx.x;

    const float* base = g_qkv + (size_t)win * (NTOK * QROW);
    {
        const float4* krow = (const float4*)(base + (size_t)i * QROW + DIMC + h * HD);
        const float4* vrow = (const float4*)(base + (size_t)i * QROW + 2 * DIMC + h * HD);
        #pragma unroll
        for (int m = 0; m < 8; m++) {
            ((float4*)Ks[i])[m] = krow[m];
            ((float4*)Vs[i])[m] = vrow[m];
        }
    }
    for (int idx = i; idx < 225; idx += 64) rpbs[idx] = rpb_table[idx * HEADS + h];
    {
        int iy = i >> 3, ix = i & 7;
        int yt = wy * 8 + iy, xt = wx * 8 + ix;
        int ry = (yt < 248) ? 0 : ((yt < 252) ? 1 : 2);
        int rx = (xt < 248) ? 0 : ((xt < 252) ? 1 : 2);
        regsh[i] = ry * 3 + rx;
    }

    u64 q2[16];
    {
        const ulonglong2* qp = (const ulonglong2*)(base + (size_t)i * QROW + h * HD);
        #pragma unroll
        for (int m = 0; m < 8; m++) {
            ulonglong2 v = qp[m];
            q2[2 * m] = v.x; q2[2 * m + 1] = v.y;
        }
    }
    __syncthreads();

    int iy = i >> 3, ix = i & 7;
    int regi = regsh[i];
    int rb = (iy + 7) * 15 + (ix + 7);

    float l = 0.f;
    u64 acc2[16];
    #pragma unroll
    for (int dp = 0; dp < 16; dp++) acc2[dp] = 0ull;

    #pragma unroll 2
    for (int j = 0; j < NTOK; j++) {
        const ulonglong2* kp = (const ulonglong2*)Ks[j];
        u64 s2 = 0ull;
        #pragma unroll
        for (int m = 0; m < 8; m++) {
            ulonglong2 kv = kp[m];
            ffma2(s2, q2[2 * m], kv.x);
            ffma2(s2, q2[2 * m + 1], kv.y);
        }
        float2 sp = unpack2(s2);
        float s = sp.x + sp.y;
        float bias = rpbs[rb - (j >> 3) * 15 - (j & 7)];
        float msk  = (regi != regsh[j]) ? -100.f : 0.f;
        float e = __expf(fmaf(s, SCALE, bias + msk));
        l += e;
        u64 es = splat2(e);
        const ulonglong2* vp = (const ulonglong2*)Vs[j];
        #pragma unroll
        for (int m = 0; m < 8; m++) {
            ulonglong2 vv = vp[m];
            ffma2(acc2[2 * m], es, vv.x);
            ffma2(acc2[2 * m + 1], es, vv.y);
        }
    }

    float invl = 1.f / l;
    float* Og = g_o + (size_t)win * (DIMC * NTOK) + (size_t)(h * HD) * 64 + i;
    #pragma unroll
    for (int dp = 0; dp < 16; dp++) {
        float2 v = unpack2(acc2[dp]);
        Og[(2 * dp) * 64]     = v.x * invl;   // coalesced across i per channel
        Og[(2 * dp + 1) * 64] = v.y * invl;
    }
}

// ---------------- kernel 3: proj GEMM + reverse-shift scatter -----------------
// warp = 8 tokens (window row), lane = 6 output channels; token-pair packing? no:
// acc[cp][t]: cp packs channel pairs (ob+2cp, ob+2cp+1) at token t.
__global__ __launch_bounds__(256, 2) void proj_kernel(const float* __restrict__ proj_b,
                                                      float* __restrict__ out) {
    __shared__ float Os[DIMC * NTOK];  // [c][t] 48KB
    int win = blockIdx.x;
    int b = win >> 10, wy = (win >> 5) & 31, wx = win & 31;
    int tid = threadIdx.x;
    int lane = tid & 31, warp = tid >> 5;

    const float* src = g_o + (size_t)win * (DIMC * NTOK);
    for (int idx = tid; idx < DIMC * NTOK / 4; idx += 256)
        ((float4*)Os)[idx] = ((const float4*)src)[idx];
    __syncthreads();

    int t0 = warp * 8;
    int ob = lane * 6;
    u64 acc[3][8];
    {
        const u64* bp = (const u64*)&proj_b[ob];   // 24B offset: 8B aligned
        #pragma unroll
        for (int cp = 0; cp < 3; cp++) {
            u64 bv = bp[cp];
            #pragma unroll
            for (int t = 0; t < 8; t++) acc[cp][t] = bv;
        }
    }
    const float* __restrict__ pT = g_pT;
    #pragma unroll 4
    for (int k = 0; k < DIMC; k++) {
        float4 a01 = *(const float4*)&Os[k * 64 + t0];
        float4 a23 = *(const float4*)&Os[k * 64 + t0 + 4];
        const u64* wr = (const u64*)&pT[k * DIMC + ob];
        u64 w0 = wr[0], w1 = wr[1], w2 = wr[2];
        u64 as[8];
        as[0] = splat2(a01.x); as[1] = splat2(a01.y);
        as[2] = splat2(a01.z); as[3] = splat2(a01.w);
        as[4] = splat2(a23.x); as[5] = splat2(a23.y);
        as[6] = splat2(a23.z); as[7] = splat2(a23.w);
        #pragma unroll
        for (int t = 0; t < 8; t++) {
            ffma2(acc[0][t], w0, as[t]);
            ffma2(acc[1][t], w1, as[t]);
            ffma2(acc[2][t], w2, as[t]);
        }
    }
    // scatter with reverse shift: tokens t0..t0+7 = window row `warp`
    int yy  = (wy * 8 + warp + SSH) & 255;
    int xx0 = wx * 8 + SSH;            // <= 252, 16B aligned
    int xx1 = (xx0 + 4) & 255;         // may wrap to 0, stays aligned
    size_t rowbase = (size_t)(b * DIMC + ob) * 65536 + (size_t)yy * 256;
    #pragma unroll
    for (int cp = 0; cp < 3; cp++) {
        float2 u0 = unpack2(acc[cp][0]), u1 = unpack2(acc[cp][1]);
        float2 u2 = unpack2(acc[cp][2]), u3 = unpack2(acc[cp][3]);
        float2 u4 = unpack2(acc[cp][4]), u5 = unpack2(acc[cp][5]);
        float2 u6 = unpack2(acc[cp][6]), u7 = unpack2(acc[cp][7]);
        size_t r0 = rowbase + (size_t)(2 * cp) * 65536;
        size_t r1 = rowbase + (size_t)(2 * cp + 1) * 65536;
        *(float4*)&out[r0 + xx0] = make_float4(u0.x, u1.x, u2.x, u3.x);
        *(float4*)&out[r0 + xx1] = make_float4(u4.x, u5.x, u6.x, u7.x);
        *(float4*)&out[r1 + xx0] = make_float4(u0.y, u1.y, u2.y, u3.y);
        *(float4*)&out[r1 + xx1] = make_float4(u4.y, u5.y, u6.y, u7.y);
    }
}

// ---------------- launch ------------------------------------------------------
extern "C" void kernel_launch(void* const* d_in, const int* in_sizes, int n_in,
                              void* d_out, int out_size) {
    const float* x      = (const float*)d_in[0];
    const float* qkv_w  = (const float*)d_in[1];
    const float* qkv_b  = (const float*)d_in[2];
    const float* proj_w = (const float*)d_in[3];
    const float* proj_b = (const float*)d_in[4];
    const float* rpb    = (const float*)d_in[5];
    float* out = (float*)d_out;

    transpose_weights<<<432, 256>>>(qkv_w, proj_w);
    qkv_kernel<<<NWIN, 256>>>(x, qkv_b);
    attn_kernel<<<dim3(NWIN, HEADS), 64>>>(rpb);
    proj_kernel<<<NWIN, 256>>>(proj_b, out);
}

// round 15
// speedup vs baseline: 1.7098x; 1.7098x over previous
#include <cuda_runtime.h>
#include <cuda_bf16.h>

#define HEADS 6
#define QROW 576
#define NTOK 64
#define SCALE 0.17677669529663687f   // 32^-0.5

typedef unsigned int u32;
typedef unsigned long long u64;
typedef unsigned short u16;

// ---------------- scratch (device globals; no allocations) -------------------
__device__ float g_qkv[(size_t)262144 * QROW];          // [win*64+t][o]  604MB
__device__ __align__(16) u32 g_oAh[(size_t)262144 * 96]; // attn out hi (bf16x2) [row][96]
__device__ __align__(16) u32 g_oAl[(size_t)262144 * 96]; // attn out lo
__device__ __align__(16) u16 g_wQh[576 * 192];           // qkv W hi [o][k]
__device__ __align__(16) u16 g_wQl[576 * 192];
__device__ __align__(16) u16 g_wPh[192 * 192];           // proj W hi [o][k]
__device__ __align__(16) u16 g_wPl[192 * 192];

// ---------------- helpers ------------------------------------------------------
__device__ __forceinline__ u32 smem_u32(const void* p) {
    u32 a; asm("{ .reg .u64 t; cvta.to.shared.u64 t, %1; cvt.u32.u64 %0, t; }"
               : "=r"(a) : "l"(p));
    return a;
}
__device__ __forceinline__ void ldm4(u32* r, u32 addr) {
    asm volatile("ldmatrix.sync.aligned.m8n8.x4.shared.b16 {%0,%1,%2,%3}, [%4];"
                 : "=r"(r[0]), "=r"(r[1]), "=r"(r[2]), "=r"(r[3]) : "r"(addr));
}
__device__ __forceinline__ void mma16816(float* c, const u32* a, const u32* b) {
    asm volatile("mma.sync.aligned.m16n8k16.row.col.f32.bf16.bf16.f32 "
                 "{%0,%1,%2,%3}, {%4,%5,%6,%7}, {%8,%9}, {%0,%1,%2,%3};"
                 : "+f"(c[0]), "+f"(c[1]), "+f"(c[2]), "+f"(c[3])
                 : "r"(a[0]), "r"(a[1]), "r"(a[2]), "r"(a[3]), "r"(b[0]), "r"(b[1]));
}
__device__ __forceinline__ u32 packbf(float a, float b) {
    __nv_bfloat16 ha = __float2bfloat16(a), hb = __float2bfloat16(b);
    return (u32)__bfloat16_as_ushort(ha) | ((u32)__bfloat16_as_ushort(hb) << 16);
}
// f32x2 helpers (attention)
__device__ __forceinline__ u64 splat2(float v) {
    u64 r; asm("mov.b64 %0,{%1,%1};" : "=l"(r) : "f"(v)); return r;
}
__device__ __forceinline__ void ffma2(u64& d, u64 a, u64 b) {
    asm("fma.rn.f32x2 %0,%1,%2,%0;" : "+l"(d) : "l"(a), "l"(b));
}
__device__ __forceinline__ float2 unpack2(u64 v) {
    float2 r; asm("mov.b64 {%0,%1},%2;" : "=f"(r.x), "=f"(r.y) : "l"(v)); return r;
}

// smem plane offsets (bytes): padded bf16 planes, row stride 200 halves (400B)
#define A_HI 0
#define A_LO 51200
#define B_HI 102400
#define B_LO 128000
#define SMEM_SZ 153600

// ---------------- kernel 0: split weights hi/lo --------------------------------
__global__ void prep_weights(const float* __restrict__ qkv_w,
                             const float* __restrict__ proj_w) {
    int idx = blockIdx.x * 256 + threadIdx.x;
    if (idx < 576 * 192) {
        float v = qkv_w[idx];
        __nv_bfloat16 h = __float2bfloat16(v);
        g_wQh[idx] = __bfloat16_as_ushort(h);
        g_wQl[idx] = __bfloat16_as_ushort(__float2bfloat16(v - __bfloat162float(h)));
    }
    if (idx < 192 * 192) {
        float v = proj_w[idx];
        __nv_bfloat16 h = __float2bfloat16(v);
        g_wPh[idx] = __bfloat16_as_ushort(h);
        g_wPl[idx] = __bfloat16_as_ushort(__float2bfloat16(v - __bfloat162float(h)));
    }
}

// ---------------- shared GEMM core (warp mma, hi/lo compensated) ---------------
// Computes C[128][64] += A[128][192] * B[64][192]^T for one n-chunk; A/B staged.
// Warp w: mblk=(w&3)*32, nblk=(w>>2)*32; returns C frags in cc[2][4][4].
__device__ __forceinline__ void gemm_chunk(char* sm, u32 smb, int lane, int wid,
                                           float cc[2][4][4]) {
    int mblk = (wid & 3) * 32, nblk = (wid >> 2) * 32;
    u32 aH = smb + A_HI + ((mblk + (lane & 15)) * 200 + (lane >> 4) * 8) * 2;
    u32 aL = aH + (A_LO - A_HI);
    int nrow = (lane & 7) + ((lane >> 4) * 8);
    int koff = ((lane >> 3) & 1) * 8;
    u32 bH = smb + B_HI + ((nblk + nrow) * 200 + koff) * 2;
    u32 bL = bH + (B_LO - B_HI);

    #pragma unroll
    for (int ks = 0; ks < 12; ks++) {
        int kb = ks * 32;  // 16 halves = 32 bytes per k-step
        u32 Ah[2][4], Al[2][4], Bh[2][4], Bl[2][4];
        ldm4(Ah[0], aH + kb); ldm4(Ah[1], aH + kb + 6400);
        ldm4(Al[0], aL + kb); ldm4(Al[1], aL + kb + 6400);
        ldm4(Bh[0], bH + kb); ldm4(Bh[1], bH + kb + 6400);
        ldm4(Bl[0], bL + kb); ldm4(Bl[1], bL + kb + 6400);
        #pragma unroll
        for (int mt = 0; mt < 2; mt++) {
            #pragma unroll
            for (int nt = 0; nt < 4; nt++) {
                const u32* bh = &Bh[nt >> 1][(nt & 1) * 2];
                const u32* bl = &Bl[nt >> 1][(nt & 1) * 2];
                mma16816(cc[mt][nt], Ah[mt], bh);
                mma16816(cc[mt][nt], Ah[mt], bl);
                mma16816(cc[mt][nt], Al[mt], bh);
            }
        }
    }
}

// ---------------- kernel 1: gather + QKV GEMM ----------------------------------
__global__ __launch_bounds__(256, 1) void qkv_kernel(const float* __restrict__ x,
                                                     const float* __restrict__ qkv_b) {
    extern __shared__ __align__(16) char sm[];
    u32 smb = smem_u32(sm);
    int tid = threadIdx.x, lane = tid & 31, wid = tid >> 5;
    int wp = blockIdx.x, win0 = wp * 2;
    int b = win0 >> 10, wy = (win0 >> 5) & 31, wx0 = win0 & 31;

    // stage A: gather shifted window, split hi/lo into padded bf16 planes
    for (int idx = tid; idx < 128 * 96; idx += 256) {
        int r = idx & 127, pr = idx >> 7;
        int c0 = pr * 2;
        int wxx = wx0 + (r >> 6);
        int t = r & 63;
        int yy = (wy * 8 + (t >> 3) + 4) & 255;
        int xx = (wxx * 8 + (t & 7) + 4) & 255;
        const float* xp = x + ((size_t)(b * 192 + c0)) * 65536 + yy * 256 + xx;
        float v0 = xp[0], v1 = xp[65536];
        __nv_bfloat16 h0 = __float2bfloat16(v0), h1 = __float2bfloat16(v1);
        float r0 = v0 - __bfloat162float(h0), r1 = v1 - __bfloat162float(h1);
        int off = r * 400 + c0 * 2;
        *(u32*)(sm + A_HI + off) =
            (u32)__bfloat16_as_ushort(h0) | ((u32)__bfloat16_as_ushort(h1) << 16);
        *(u32*)(sm + A_LO + off) = packbf(r0, r1);
    }

    int g = lane >> 2, tig = lane & 3;
    int mblk = (wid & 3) * 32, nblk = (wid >> 2) * 32;

    for (int nc = 0; nc < 9; nc++) {
        __syncthreads();   // prior chunk's mma done before B overwrite (and A ready)
        // stage B: rows nc*64..+63 of [o][k] hi/lo into padded planes
        for (int i = tid; i < 1536; i += 256) {
            int row = i / 24, seg = i % 24;
            int off = row * 400 + seg * 16;
            *(uint4*)(sm + B_HI + off) =
                ((const uint4*)g_wQh)[(size_t)(nc * 64 + row) * 24 + seg];
            *(uint4*)(sm + B_LO + off) =
                ((const uint4*)g_wQl)[(size_t)(nc * 64 + row) * 24 + seg];
        }
        __syncthreads();

        float cc[2][4][4];
        #pragma unroll
        for (int mt = 0; mt < 2; mt++)
            #pragma unroll
            for (int nt = 0; nt < 4; nt++)
                #pragma unroll
                for (int q = 0; q < 4; q++) cc[mt][nt][q] = 0.f;

        gemm_chunk(sm, smb, lane, wid, cc);

        // epilogue: +bias, write [t][o] rows
        #pragma unroll
        for (int mt = 0; mt < 2; mt++) {
            int row0 = mblk + mt * 16 + g;
            #pragma unroll
            for (int nt = 0; nt < 4; nt++) {
                int o = nc * 64 + nblk + nt * 8 + tig * 2;
                float2 bo = *(const float2*)&qkv_b[o];
                size_t base = (size_t)(wp * 128 + row0) * QROW + o;
                float2 v0 = make_float2(cc[mt][nt][0] + bo.x, cc[mt][nt][1] + bo.y);
                float2 v1 = make_float2(cc[mt][nt][2] + bo.x, cc[mt][nt][3] + bo.y);
                *(float2*)&g_qkv[base]            = v0;
                *(float2*)&g_qkv[base + 8 * QROW] = v1;
            }
        }
    }
}

// ---------------- kernel 2: windowed attention (fp32, verified) ----------------
// grid (4096, 6), 64 threads; epilogue emits bf16 hi/lo proj-A rows.
__global__ __launch_bounds__(64) void attn_kernel(const float* __restrict__ rpb_table) {
    __shared__ float Ks[NTOK][32];
    __shared__ float Vs[NTOK][32];
    __shared__ float rpbs[225];
    __shared__ int   regsh[NTOK];

    int win = blockIdx.x, h = blockIdx.y;
    int wy = (win >> 5) & 31, wx = win & 31;
    int i = threadIdx.x;

    const float* base = g_qkv + (size_t)win * (NTOK * QROW);
    {
        const float4* krow = (const float4*)(base + (size_t)i * QROW + 192 + h * 32);
        const float4* vrow = (const float4*)(base + (size_t)i * QROW + 384 + h * 32);
        #pragma unroll
        for (int m = 0; m < 8; m++) {
            ((float4*)Ks[i])[m] = krow[m];
            ((float4*)Vs[i])[m] = vrow[m];
        }
    }
    for (int idx = i; idx < 225; idx += 64) rpbs[idx] = rpb_table[idx * HEADS + h];
    {
        int iy = i >> 3, ix = i & 7;
        int yt = wy * 8 + iy, xt = wx * 8 + ix;
        int ry = (yt < 248) ? 0 : ((yt < 252) ? 1 : 2);
        int rx = (xt < 248) ? 0 : ((xt < 252) ? 1 : 2);
        regsh[i] = ry * 3 + rx;
    }

    u64 q2[16];
    {
        const ulonglong2* qp = (const ulonglong2*)(base + (size_t)i * QROW + h * 32);
        #pragma unroll
        for (int m = 0; m < 8; m++) {
            ulonglong2 v = qp[m];
            q2[2 * m] = v.x; q2[2 * m + 1] = v.y;
        }
    }
    __syncthreads();

    int iy = i >> 3, ix = i & 7;
    int regi = regsh[i];
    int rb = (iy + 7) * 15 + (ix + 7);

    float l = 0.f;
    u64 acc2[16];
    #pragma unroll
    for (int dp = 0; dp < 16; dp++) acc2[dp] = 0ull;

    #pragma unroll 2
    for (int j = 0; j < NTOK; j++) {
        const ulonglong2* kp = (const ulonglong2*)Ks[j];
        u64 s2 = 0ull;
        #pragma unroll
        for (int m = 0; m < 8; m++) {
            ulonglong2 kv = kp[m];
            ffma2(s2, q2[2 * m], kv.x);
            ffma2(s2, q2[2 * m + 1], kv.y);
        }
        float2 sp = unpack2(s2);
        float s = sp.x + sp.y;
        float bias = rpbs[rb - (j >> 3) * 15 - (j & 7)];
        float msk  = (regi != regsh[j]) ? -100.f : 0.f;
        float e = __expf(fmaf(s, SCALE, bias + msk));
        l += e;
        u64 es = splat2(e);
        const ulonglong2* vp = (const ulonglong2*)Vs[j];
        #pragma unroll
        for (int m = 0; m < 8; m++) {
            ulonglong2 vv = vp[m];
            ffma2(acc2[2 * m], es, vv.x);
            ffma2(acc2[2 * m + 1], es, vv.y);
        }
    }

    // epilogue: normalize, hi/lo split, write bf16x2 rows [row][96 u32]
    float invl = 1.f / l;
    u32 hiw[16], low[16];
    #pragma unroll
    for (int dp = 0; dp < 16; dp++) {
        float2 v = unpack2(acc2[dp]);
        v.x *= invl; v.y *= invl;
        __nv_bfloat16 h0 = __float2bfloat16(v.x), h1 = __float2bfloat16(v.y);
        hiw[dp] = (u32)__bfloat16_as_ushort(h0) | ((u32)__bfloat16_as_ushort(h1) << 16);
        low[dp] = packbf(v.x - __bfloat162float(h0), v.y - __bfloat162float(h1));
    }
    size_t rbase = (size_t)(win * 64 + i) * 96 + h * 16;
    #pragma unroll
    for (int m = 0; m < 4; m++) {
        *(uint4*)&g_oAh[rbase + m * 4] =
            make_uint4(hiw[4 * m], hiw[4 * m + 1], hiw[4 * m + 2], hiw[4 * m + 3]);
        *(uint4*)&g_oAl[rbase + m * 4] =
            make_uint4(low[4 * m], low[4 * m + 1], low[4 * m + 2], low[4 * m + 3]);
    }
}

// ---------------- kernel 3: proj GEMM + reverse-shift scatter ------------------
__global__ __launch_bounds__(256, 1) void proj_kernel(const float* __restrict__ proj_b,
                                                      float* __restrict__ out) {
    extern __shared__ __align__(16) char sm[];
    u32 smb = smem_u32(sm);
    int tid = threadIdx.x, lane = tid & 31, wid = tid >> 5;
    int wp = blockIdx.x, win0 = wp * 2;
    int b = win0 >> 10, wy = (win0 >> 5) & 31, wx0 = win0 & 31;

    // stage A: copy pre-split attn output rows (stride 192 -> 200 halves)
    for (int i = tid; i < 3072; i += 256) {
        int row = i / 24, seg = i % 24;
        int off = row * 400 + seg * 16;
        *(uint4*)(sm + A_HI + off) =
            ((const uint4*)g_oAh)[(size_t)(wp * 128 + row) * 24 + seg];
        *(uint4*)(sm + A_LO + off) =
            ((const uint4*)g_oAl)[(size_t)(wp * 128 + row) * 24 + seg];
    }

    int g = lane >> 2, tig = lane & 3;
    int mblk = (wid & 3) * 32, nblk = (wid >> 2) * 32;

    for (int nc = 0; nc < 3; nc++) {
        __syncthreads();
        for (int i = tid; i < 1536; i += 256) {
            int row = i / 24, seg = i % 24;
            int off = row * 400 + seg * 16;
            *(uint4*)(sm + B_HI + off) =
                ((const uint4*)g_wPh)[(size_t)(nc * 64 + row) * 24 + seg];
            *(uint4*)(sm + B_LO + off) =
                ((const uint4*)g_wPl)[(size_t)(nc * 64 + row) * 24 + seg];
        }
        __syncthreads();

        float cc[2][4][4];
        #pragma unroll
        for (int mt = 0; mt < 2; mt++)
            #pragma unroll
            for (int nt = 0; nt < 4; nt++)
                #pragma unroll
                for (int q = 0; q < 4; q++) cc[mt][nt][q] = 0.f;

        gemm_chunk(sm, smb, lane, wid, cc);

        // epilogue: +bias, reverse-shift NCHW scatter
        #pragma unroll
        for (int mt = 0; mt < 2; mt++) {
            int row0 = mblk + mt * 16 + g;
            int wxx = wx0 + (row0 >> 6);
            int t0 = row0 & 63, t1 = (row0 + 8) & 63;
            int yy0 = (wy * 8 + (t0 >> 3) + 4) & 255;
            int yy1 = (wy * 8 + (t1 >> 3) + 4) & 255;
            int xx  = (wxx * 8 + (t0 & 7) + 4) & 255;   // same ix for both rows
            size_t p0 = (size_t)yy0 * 256 + xx;
            size_t p1 = (size_t)yy1 * 256 + xx;
            #pragma unroll
            for (int nt = 0; nt < 4; nt++) {
                int o = nc * 64 + nblk + nt * 8 + tig * 2;
                float2 bo = *(const float2*)&proj_b[o];
                size_t c0 = (size_t)(b * 192 + o) * 65536;
                size_t c1 = c0 + 65536;
                out[c0 + p0] = cc[mt][nt][0] + bo.x;
                out[c1 + p0] = cc[mt][nt][1] + bo.y;
                out[c0 + p1] = cc[mt][nt][2] + bo.x;
                out[c1 + p1] = cc[mt][nt][3] + bo.y;
            }
        }
    }
}

// ---------------- launch --------------------------------------------------------
extern "C" void kernel_launch(void* const* d_in, const int* in_sizes, int n_in,
                              void* d_out, int out_size) {
    const float* x      = (const float*)d_in[0];
    const float* qkv_w  = (const float*)d_in[1];
    const float* qkv_b  = (const float*)d_in[2];
    const float* proj_w = (const float*)d_in[3];
    const float* proj_b = (const float*)d_in[4];
    const float* rpb    = (const float*)d_in[5];
    float* out = (float*)d_out;

    cudaFuncSetAttribute(qkv_kernel, cudaFuncAttributeMaxDynamicSharedMemorySize, SMEM_SZ);
    cudaFuncSetAttribute(proj_kernel, cudaFuncAttributeMaxDynamicSharedMemorySize, SMEM_SZ);

    prep_weights<<<432, 256>>>(qkv_w, proj_w);
    qkv_kernel<<<2048, 256, SMEM_SZ>>>(x, qkv_b);
    attn_kernel<<<dim3(4096, HEADS), 64>>>(rpb);
    proj_kernel<<<2048, 256, SMEM_SZ>>>(proj_b, out);
}

// round 16
// speedup vs baseline: 1.8695x; 1.0934x over previous
#include <cuda_runtime.h>
#include <cuda_bf16.h>

#define HEADS 6
#define QROW 576
#define NTOK 64
#define SCALE 0.17677669529663687f   // 32^-0.5

typedef unsigned int u32;
typedef unsigned long long u64;
typedef unsigned short u16;

// ---------------- scratch (device globals; no allocations) -------------------
__device__ float g_qkv[(size_t)262144 * QROW];          // [win*64+t][o]  604MB
__device__ __align__(16) u32 g_oAh[(size_t)262144 * 96]; // attn out hi (bf16x2) [row][96]
__device__ __align__(16) u32 g_oAl[(size_t)262144 * 96]; // attn out lo
__device__ __align__(16) u16 g_wQh[576 * 192];           // qkv W hi [o][k]
__device__ __align__(16) u16 g_wQl[576 * 192];
__device__ __align__(16) u16 g_wPh[192 * 192];           // proj W hi [o][k]
__device__ __align__(16) u16 g_wPl[192 * 192];

// ---------------- helpers ------------------------------------------------------
__device__ __forceinline__ u32 smem_u32(const void* p) {
    u32 a; asm("{ .reg .u64 t; cvta.to.shared.u64 t, %1; cvt.u32.u64 %0, t; }"
               : "=r"(a) : "l"(p));
    return a;
}
__device__ __forceinline__ void ldm4(u32* r, u32 addr) {
    asm volatile("ldmatrix.sync.aligned.m8n8.x4.shared.b16 {%0,%1,%2,%3}, [%4];"
                 : "=r"(r[0]), "=r"(r[1]), "=r"(r[2]), "=r"(r[3]) : "r"(addr));
}
__device__ __forceinline__ void mma16816(float* c, const u32* a, const u32* b) {
    asm volatile("mma.sync.aligned.m16n8k16.row.col.f32.bf16.bf16.f32 "
                 "{%0,%1,%2,%3}, {%4,%5,%6,%7}, {%8,%9}, {%0,%1,%2,%3};"
                 : "+f"(c[0]), "+f"(c[1]), "+f"(c[2]), "+f"(c[3])
                 : "r"(a[0]), "r"(a[1]), "r"(a[2]), "r"(a[3]), "r"(b[0]), "r"(b[1]));
}
__device__ __forceinline__ u32 packbf(float a, float b) {
    __nv_bfloat16 ha = __float2bfloat16(a), hb = __float2bfloat16(b);
    return (u32)__bfloat16_as_ushort(ha) | ((u32)__bfloat16_as_ushort(hb) << 16);
}
// f32x2 helpers (attention)
__device__ __forceinline__ u64 splat2(float v) {
    u64 r; asm("mov.b64 %0,{%1,%1};" : "=l"(r) : "f"(v)); return r;
}
__device__ __forceinline__ void ffma2(u64& d, u64 a, u64 b) {
    asm("fma.rn.f32x2 %0,%1,%2,%0;" : "+l"(d) : "l"(a), "l"(b));
}
__device__ __forceinline__ float2 unpack2(u64 v) {
    float2 r; asm("mov.b64 {%0,%1},%2;" : "=f"(r.x), "=f"(r.y) : "l"(v)); return r;
}

// smem plane offsets (bytes): padded bf16 planes, row stride 200 halves (400B)
// M=64 per CTA: A planes 64 rows, B planes 64 rows -> 102.4KB total, 2 CTAs/SM
#define A_HI 0
#define A_LO 25600
#define B_HI 51200
#define B_LO 76800
#define SMEM_SZ 102400

// ---------------- kernel 0: split weights hi/lo --------------------------------
__global__ void prep_weights(const float* __restrict__ qkv_w,
                             const float* __restrict__ proj_w) {
    int idx = blockIdx.x * 256 + threadIdx.x;
    if (idx < 576 * 192) {
        float v = qkv_w[idx];
        __nv_bfloat16 h = __float2bfloat16(v);
        g_wQh[idx] = __bfloat16_as_ushort(h);
        g_wQl[idx] = __bfloat16_as_ushort(__float2bfloat16(v - __bfloat162float(h)));
    }
    if (idx < 192 * 192) {
        float v = proj_w[idx];
        __nv_bfloat16 h = __float2bfloat16(v);
        g_wPh[idx] = __bfloat16_as_ushort(h);
        g_wPl[idx] = __bfloat16_as_ushort(__float2bfloat16(v - __bfloat162float(h)));
    }
}

// ---------------- shared GEMM core (warp mma, hi/lo compensated) ---------------
// C[64][64] += A[64][192] * B[64][192]^T for one n-chunk.
// Warp w: mblk=(w&3)*16, nblk=(w>>2)*32; C frags in cc[4][4].
__device__ __forceinline__ void gemm_chunk(u32 smb, int lane, int wid,
                                           float cc[4][4]) {
    int mblk = (wid & 3) * 16, nblk = (wid >> 2) * 32;
    u32 aH = smb + A_HI + ((mblk + (lane & 15)) * 200 + (lane >> 4) * 8) * 2;
    u32 aL = aH + (A_LO - A_HI);
    int nrow = (lane & 7) + ((lane >> 4) * 8);
    int koff = ((lane >> 3) & 1) * 8;
    u32 bH = smb + B_HI + ((nblk + nrow) * 200 + koff) * 2;
    u32 bL = bH + (B_LO - B_HI);

    #pragma unroll
    for (int ks = 0; ks < 12; ks++) {
        int kb = ks * 32;  // 16 halves = 32 bytes per k-step
        u32 Ah[4], Al[4], Bh[2][4], Bl[2][4];
        ldm4(Ah, aH + kb);
        ldm4(Al, aL + kb);
        ldm4(Bh[0], bH + kb); ldm4(Bh[1], bH + kb + 6400);  // +16 n-rows
        ldm4(Bl[0], bL + kb); ldm4(Bl[1], bL + kb + 6400);
        #pragma unroll
        for (int nt = 0; nt < 4; nt++) {
            const u32* bh = &Bh[nt >> 1][(nt & 1) * 2];
            const u32* bl = &Bl[nt >> 1][(nt & 1) * 2];
            mma16816(cc[nt], Ah, bh);
            mma16816(cc[nt], Ah, bl);
            mma16816(cc[nt], Al, bh);
        }
    }
}

// ---------------- kernel 1: gather + QKV GEMM ----------------------------------
// One CTA per window (M=64 token rows), 9 n-chunks of 64.
__global__ __launch_bounds__(256, 2) void qkv_kernel(const float* __restrict__ x,
                                                     const float* __restrict__ qkv_b) {
    extern __shared__ __align__(16) char sm[];
    u32 smb = smem_u32(sm);
    int tid = threadIdx.x, lane = tid & 31, wid = tid >> 5;
    int win = blockIdx.x;
    int b = win >> 10, wy = (win >> 5) & 31, wx = win & 31;

    // stage A: gather shifted window, split hi/lo into padded bf16 planes
    for (int idx = tid; idx < 64 * 96; idx += 256) {
        int t = idx & 63, pr = idx >> 6;
        int c0 = pr * 2;
        int yy = (wy * 8 + (t >> 3) + 4) & 255;
        int xx = (wx * 8 + (t & 7) + 4) & 255;
        const float* xp = x + ((size_t)(b * 192 + c0)) * 65536 + yy * 256 + xx;
        float v0 = xp[0], v1 = xp[65536];
        __nv_bfloat16 h0 = __float2bfloat16(v0), h1 = __float2bfloat16(v1);
        float r0 = v0 - __bfloat162float(h0), r1 = v1 - __bfloat162float(h1);
        int off = t * 400 + c0 * 2;
        *(u32*)(sm + A_HI + off) =
            (u32)__bfloat16_as_ushort(h0) | ((u32)__bfloat16_as_ushort(h1) << 16);
        *(u32*)(sm + A_LO + off) = packbf(r0, r1);
    }

    int g = lane >> 2, tig = lane & 3;
    int mblk = (wid & 3) * 16, nblk = (wid >> 2) * 32;

    for (int nc = 0; nc < 9; nc++) {
        __syncthreads();   // prior chunk's mma done before B overwrite (and A ready)
        // stage B: rows nc*64..+63 of [o][k] hi/lo into padded planes
        for (int i = tid; i < 1536; i += 256) {
            int row = i / 24, seg = i % 24;
            int off = row * 400 + seg * 16;
            *(uint4*)(sm + B_HI + off) =
                ((const uint4*)g_wQh)[(size_t)(nc * 64 + row) * 24 + seg];
            *(uint4*)(sm + B_LO + off) =
                ((const uint4*)g_wQl)[(size_t)(nc * 64 + row) * 24 + seg];
        }
        __syncthreads();

        float cc[4][4];
        #pragma unroll
        for (int nt = 0; nt < 4; nt++)
            #pragma unroll
            for (int q = 0; q < 4; q++) cc[nt][q] = 0.f;

        gemm_chunk(smb, lane, wid, cc);

        // epilogue: +bias, write [t][o] rows
        int row0 = mblk + g;
        #pragma unroll
        for (int nt = 0; nt < 4; nt++) {
            int o = nc * 64 + nblk + nt * 8 + tig * 2;
            float2 bo = *(const float2*)&qkv_b[o];
            size_t base = (size_t)(win * 64 + row0) * QROW + o;
            *(float2*)&g_qkv[base] =
                make_float2(cc[nt][0] + bo.x, cc[nt][1] + bo.y);
            *(float2*)&g_qkv[base + 8 * QROW] =
                make_float2(cc[nt][2] + bo.x, cc[nt][3] + bo.y);
        }
    }
}

// ---------------- kernel 2: windowed attention (fp32, verified) ----------------
// grid (4096, 6), 64 threads; epilogue emits bf16 hi/lo proj-A rows.
__global__ __launch_bounds__(64) void attn_kernel(const float* __restrict__ rpb_table) {
    __shared__ float Ks[NTOK][32];
    __shared__ float Vs[NTOK][32];
    __shared__ float rpbs[225];
    __shared__ int   regsh[NTOK];

    int win = blockIdx.x, h = blockIdx.y;
    int wy = (win >> 5) & 31, wx = win & 31;
    int i = threadIdx.x;

    const float* base = g_qkv + (size_t)win * (NTOK * QROW);
    {
        const float4* krow = (const float4*)(base + (size_t)i * QROW + 192 + h * 32);
        const float4* vrow = (const float4*)(base + (size_t)i * QROW + 384 + h * 32);
        #pragma unroll
        for (int m = 0; m < 8; m++) {
            ((float4*)Ks[i])[m] = krow[m];
            ((float4*)Vs[i])[m] = vrow[m];
        }
    }
    for (int idx = i; idx < 225; idx += 64) rpbs[idx] = rpb_table[idx * HEADS + h];
    {
        int iy = i >> 3, ix = i & 7;
        int yt = wy * 8 + iy, xt = wx * 8 + ix;
        int ry = (yt < 248) ? 0 : ((yt < 252) ? 1 : 2);
        int rx = (xt < 248) ? 0 : ((xt < 252) ? 1 : 2);
        regsh[i] = ry * 3 + rx;
    }

    u64 q2[16];
    {
        const ulonglong2* qp = (const ulonglong2*)(base + (size_t)i * QROW + h * 32);
        #pragma unroll
        for (int m = 0; m < 8; m++) {
            ulonglong2 v = qp[m];
            q2[2 * m] = v.x; q2[2 * m + 1] = v.y;
        }
    }
    __syncthreads();

    int iy = i >> 3, ix = i & 7;
    int regi = regsh[i];
    int rb = (iy + 7) * 15 + (ix + 7);

    float l = 0.f;
    u64 acc2[16];
    #pragma unroll
    for (int dp = 0; dp < 16; dp++) acc2[dp] = 0ull;

    #pragma unroll 2
    for (int j = 0; j < NTOK; j++) {
        const ulonglong2* kp = (const ulonglong2*)Ks[j];
        u64 s2 = 0ull;
        #pragma unroll
        for (int m = 0; m < 8; m++) {
            ulonglong2 kv = kp[m];
            ffma2(s2, q2[2 * m], kv.x);
            ffma2(s2, q2[2 * m + 1], kv.y);
        }
        float2 sp = unpack2(s2);
        float s = sp.x + sp.y;
        float bias = rpbs[rb - (j >> 3) * 15 - (j & 7)];
        float msk  = (regi != regsh[j]) ? -100.f : 0.f;
        float e = __expf(fmaf(s, SCALE, bias + msk));
        l += e;
        u64 es = splat2(e);
        const ulonglong2* vp = (const ulonglong2*)Vs[j];
        #pragma unroll
        for (int m = 0; m < 8; m++) {
            ulonglong2 vv = vp[m];
            ffma2(acc2[2 * m], es, vv.x);
            ffma2(acc2[2 * m + 1], es, vv.y);
        }
    }

    // epilogue: normalize, hi/lo split, write bf16x2 rows [row][96 u32]
    float invl = 1.f / l;
    u32 hiw[16], low[16];
    #pragma unroll
    for (int dp = 0; dp < 16; dp++) {
        float2 v = unpack2(acc2[dp]);
        v.x *= invl; v.y *= invl;
        __nv_bfloat16 h0 = __float2bfloat16(v.x), h1 = __float2bfloat16(v.y);
        hiw[dp] = (u32)__bfloat16_as_ushort(h0) | ((u32)__bfloat16_as_ushort(h1) << 16);
        low[dp] = packbf(v.x - __bfloat162float(h0), v.y - __bfloat162float(h1));
    }
    size_t rbase = (size_t)(win * 64 + i) * 96 + h * 16;
    #pragma unroll
    for (int m = 0; m < 4; m++) {
        *(uint4*)&g_oAh[rbase + m * 4] =
            make_uint4(hiw[4 * m], hiw[4 * m + 1], hiw[4 * m + 2], hiw[4 * m + 3]);
        *(uint4*)&g_oAl[rbase + m * 4] =
            make_uint4(low[4 * m], low[4 * m + 1], low[4 * m + 2], low[4 * m + 3]);
    }
}

// ---------------- kernel 3: proj GEMM + reverse-shift scatter ------------------
// One CTA per window (M=64), 3 n-chunks of 64.
__global__ __launch_bounds__(256, 2) void proj_kernel(const float* __restrict__ proj_b,
                                                      float* __restrict__ out) {
    extern __shared__ __align__(16) char sm[];
    u32 smb = smem_u32(sm);
    int tid = threadIdx.x, lane = tid & 31, wid = tid >> 5;
    int win = blockIdx.x;
    int b = win >> 10, wy = (win >> 5) & 31, wx = win & 31;

    // stage A: copy pre-split attn output rows (stride 192 -> 200 halves)
    for (int i = tid; i < 1536; i += 256) {
        int row = i / 24, seg = i % 24;
        int off = row * 400 + seg * 16;
        *(uint4*)(sm + A_HI + off) =
            ((const uint4*)g_oAh)[(size_t)(win * 64 + row) * 24 + seg];
        *(uint4*)(sm + A_LO + off) =
            ((const uint4*)g_oAl)[(size_t)(win * 64 + row) * 24 + seg];
    }

    int g = lane >> 2, tig = lane & 3;
    int mblk = (wid & 3) * 16, nblk = (wid >> 2) * 32;

    for (int nc = 0; nc < 3; nc++) {
        __syncthreads();
        for (int i = tid; i < 1536; i += 256) {
            int row = i / 24, seg = i % 24;
            int off = row * 400 + seg * 16;
            *(uint4*)(sm + B_HI + off) =
                ((const uint4*)g_wPh)[(size_t)(nc * 64 + row) * 24 + seg];
            *(uint4*)(sm + B_LO + off) =
                ((const uint4*)g_wPl)[(size_t)(nc * 64 + row) * 24 + seg];
        }
        __syncthreads();

        float cc[4][4];
        #pragma unroll
        for (int nt = 0; nt < 4; nt++)
            #pragma unroll
            for (int q = 0; q < 4; q++) cc[nt][q] = 0.f;

        gemm_chunk(smb, lane, wid, cc);

        // epilogue: +bias, reverse-shift NCHW scatter
        int row0 = mblk + g;          // token t of this window
        int t1 = row0 + 8;
        int yy0 = (wy * 8 + (row0 >> 3) + 4) & 255;
        int yy1 = (wy * 8 + (t1 >> 3) + 4) & 255;
        int xx  = (wx * 8 + (row0 & 7) + 4) & 255;   // same ix for both rows
        size_t p0 = (size_t)yy0 * 256 + xx;
        size_t p1 = (size_t)yy1 * 256 + xx;
        #pragma unroll
        for (int nt = 0; nt < 4; nt++) {
            int o = nc * 64 + nblk + nt * 8 + tig * 2;
            float2 bo = *(const float2*)&proj_b[o];
            size_t c0 = (size_t)(b * 192 + o) * 65536;
            size_t c1 = c0 + 65536;
            out[c0 + p0] = cc[nt][0] + bo.x;
            out[c1 + p0] = cc[nt][1] + bo.y;
            out[c0 + p1] = cc[nt][2] + bo.x;
            out[c1 + p1] = cc[nt][3] + bo.y;
        }
    }
}

// ---------------- launch --------------------------------------------------------
extern "C" void kernel_launch(void* const* d_in, const int* in_sizes, int n_in,
                              void* d_out, int out_size) {
    const float* x      = (const float*)d_in[0];
    const float* qkv_w  = (const float*)d_in[1];
    const float* qkv_b  = (const float*)d_in[2];
    const float* proj_w = (const float*)d_in[3];
    const float* proj_b = (const float*)d_in[4];
    const float* rpb    = (const float*)d_in[5];
    float* out = (float*)d_out;

    cudaFuncSetAttribute(qkv_kernel, cudaFuncAttributeMaxDynamicSharedMemorySize, SMEM_SZ);
    cudaFuncSetAttribute(proj_kernel, cudaFuncAttributeMaxDynamicSharedMemorySize, SMEM_SZ);

    prep_weights<<<432, 256>>>(qkv_w, proj_w);
    qkv_kernel<<<4096, 256, SMEM_SZ>>>(x, qkv_b);
    attn_kernel<<<dim3(4096, HEADS), 64>>>(rpb);
    proj_kernel<<<4096, 256, SMEM_SZ>>>(proj_b, out);
}

// round 17
// speedup vs baseline: 1.8802x; 1.0057x over previous
#include <cuda_runtime.h>
#include <cuda_bf16.h>

#define HEADS 6
#define QROW 576
#define NTOK 64
#define SCALE 0.17677669529663687f   // 32^-0.5

typedef unsigned int u32;
typedef unsigned long long u64;
typedef unsigned short u16;

// ---------------- scratch (device globals; no allocations) -------------------
__device__ float g_qkv[(size_t)262144 * QROW];          // [win*64+t][o]  604MB
__device__ __align__(16) u32 g_oAh[(size_t)262144 * 96]; // attn out hi (bf16x2)
__device__ __align__(16) u32 g_oAl[(size_t)262144 * 96]; // attn out lo
// fragment-ordered weights: [plane][nc][ks][n32][lane][8 u32]
__device__ __align__(16) u32 g_wQf[2 * 55296];           // qkv  (9 chunks)
__device__ __align__(16) u32 g_wPf[2 * 18432];           // proj (3 chunks)

// ---------------- helpers ------------------------------------------------------
__device__ __forceinline__ u32 smem_u32(const void* p) {
    u32 a; asm("{ .reg .u64 t; cvta.to.shared.u64 t, %1; cvt.u32.u64 %0, t; }"
               : "=r"(a) : "l"(p));
    return a;
}
__device__ __forceinline__ void ldm4(u32* r, u32 addr) {
    asm volatile("ldmatrix.sync.aligned.m8n8.x4.shared.b16 {%0,%1,%2,%3}, [%4];"
                 : "=r"(r[0]), "=r"(r[1]), "=r"(r[2]), "=r"(r[3]) : "r"(addr));
}
__device__ __forceinline__ void mma16816(float* c, const u32* a, u32 b0, u32 b1) {
    asm volatile("mma.sync.aligned.m16n8k16.row.col.f32.bf16.bf16.f32 "
                 "{%0,%1,%2,%3}, {%4,%5,%6,%7}, {%8,%9}, {%0,%1,%2,%3};"
                 : "+f"(c[0]), "+f"(c[1]), "+f"(c[2]), "+f"(c[3])
                 : "r"(a[0]), "r"(a[1]), "r"(a[2]), "r"(a[3]), "r"(b0), "r"(b1));
}
__device__ __forceinline__ u32 packbf(float a, float b) {
    __nv_bfloat16 ha = __float2bfloat16(a), hb = __float2bfloat16(b);
    return (u32)__bfloat16_as_ushort(ha) | ((u32)__bfloat16_as_ushort(hb) << 16);
}
// f32x2 helpers (attention)
__device__ __forceinline__ u64 splat2(float v) {
    u64 r; asm("mov.b64 %0,{%1,%1};" : "=l"(r) : "f"(v)); return r;
}
__device__ __forceinline__ void ffma2(u64& d, u64 a, u64 b) {
    asm("fma.rn.f32x2 %0,%1,%2,%0;" : "+l"(d) : "l"(a), "l"(b));
}
__device__ __forceinline__ float2 unpack2(u64 v) {
    float2 r; asm("mov.b64 {%0,%1},%2;" : "=f"(r.x), "=f"(r.y) : "l"(v)); return r;
}

// smem: A planes only (padded bf16, row stride 200 halves = 400B)
#define A_HI 0
#define A_LO 25600
#define SMEM_SZ 51200

// ---------------- kernel 0: weights -> fragment-ordered hi/lo -----------------
// entry idx = (((nc*12+ks)*2+n32)*32+lane)*8 + j, j = nt*2 + b1flag
// n = nc*64 + n32*32 + nt*8 + lane/4 ; k = ks*16 + (lane%4)*2 + b1flag*8
__global__ void prep_frag(const float* __restrict__ qkv_w,
                          const float* __restrict__ proj_w) {
    int idx = blockIdx.x * 256 + threadIdx.x;
    if (idx < 55296) {
        int j = idx & 7, lane = (idx >> 3) & 31, n32 = (idx >> 8) & 1;
        int ks = (idx >> 9) % 12, nc = (idx >> 9) / 12;
        int n = nc * 64 + n32 * 32 + (j >> 1) * 8 + (lane >> 2);
        int k = ks * 16 + (lane & 3) * 2 + (j & 1) * 8;
        float v0 = qkv_w[n * 192 + k], v1 = qkv_w[n * 192 + k + 1];
        __nv_bfloat16 h0 = __float2bfloat16(v0), h1 = __float2bfloat16(v1);
        g_wQf[idx] = (u32)__bfloat16_as_ushort(h0) | ((u32)__bfloat16_as_ushort(h1) << 16);
        g_wQf[55296 + idx] = packbf(v0 - __bfloat162float(h0), v1 - __bfloat162float(h1));
    }
    if (idx < 18432) {
        int j = idx & 7, lane = (idx >> 3) & 31, n32 = (idx >> 8) & 1;
        int ks = (idx >> 9) % 12, nc = (idx >> 9) / 12;
        int n = nc * 64 + n32 * 32 + (j >> 1) * 8 + (lane >> 2);
        int k = ks * 16 + (lane & 3) * 2 + (j & 1) * 8;
        float v0 = proj_w[n * 192 + k], v1 = proj_w[n * 192 + k + 1];
        __nv_bfloat16 h0 = __float2bfloat16(v0), h1 = __float2bfloat16(v1);
        g_wPf[idx] = (u32)__bfloat16_as_ushort(h0) | ((u32)__bfloat16_as_ushort(h1) << 16);
        g_wPf[18432 + idx] = packbf(v0 - __bfloat162float(h0), v1 - __bfloat162float(h1));
    }
}

// ---------------- shared GEMM core (A from smem, B frags from L2) -------------
// C[64][64] for one n-chunk. Warp w: mblk=(w&3)*16, n32=w>>2; cc[4][4].
__device__ __forceinline__ void gemm_chunk(u32 smb, int lane, int wid,
                                           const uint4* __restrict__ wfh,
                                           const uint4* __restrict__ wfl,
                                           int nc, float cc[4][4]) {
    int mblk = (wid & 3) * 16, n32 = wid >> 2;
    u32 aH = smb + A_HI + ((mblk + (lane & 15)) * 200 + (lane >> 4) * 8) * 2;
    u32 aL = aH + (A_LO - A_HI);
    // uint4 index for (nc,ks,n32,lane): (((nc*12+ks)*2+n32)*32+lane)*2
    const uint4* bh = wfh + (((size_t)(nc * 12) * 2 + n32) * 32 + lane) * 2;
    const uint4* bl = wfl + (((size_t)(nc * 12) * 2 + n32) * 32 + lane) * 2;

    #pragma unroll
    for (int ks = 0; ks < 12; ks++) {
        u32 Ah[4], Al[4];
        ldm4(Ah, aH + ks * 32);
        ldm4(Al, aL + ks * 32);
        size_t bo = (size_t)ks * 128;            // +ks*(2*32*2) uint4
        uint4 Bh0 = bh[bo], Bh1 = bh[bo + 1];
        uint4 Bl0 = bl[bo], Bl1 = bl[bo + 1];
        mma16816(cc[0], Ah, Bh0.x, Bh0.y);
        mma16816(cc[0], Ah, Bl0.x, Bl0.y);
        mma16816(cc[0], Al, Bh0.x, Bh0.y);
        mma16816(cc[1], Ah, Bh0.z, Bh0.w);
        mma16816(cc[1], Ah, Bl0.z, Bl0.w);
        mma16816(cc[1], Al, Bh0.z, Bh0.w);
        mma16816(cc[2], Ah, Bh1.x, Bh1.y);
        mma16816(cc[2], Ah, Bl1.x, Bl1.y);
        mma16816(cc[2], Al, Bh1.x, Bh1.y);
        mma16816(cc[3], Ah, Bh1.z, Bh1.w);
        mma16816(cc[3], Ah, Bl1.z, Bl1.w);
        mma16816(cc[3], Al, Bh1.z, Bh1.w);
    }
}

// ---------------- kernel 1: gather + QKV GEMM ----------------------------------
// One CTA per window (M=64), 9 n-chunks, no per-chunk barriers.
__global__ __launch_bounds__(256, 3) void qkv_kernel(const float* __restrict__ x,
                                                     const float* __restrict__ qkv_b) {
    extern __shared__ __align__(16) char sm[];
    u32 smb = smem_u32(sm);
    int tid = threadIdx.x, lane = tid & 31, wid = tid >> 5;
    int win = blockIdx.x;
    int b = win >> 10, wy = (win >> 5) & 31, wx = win & 31;

    // stage A: gather shifted window, split hi/lo into padded bf16 planes
    for (int idx = tid; idx < 64 * 96; idx += 256) {
        int t = idx & 63, pr = idx >> 6;
        int c0 = pr * 2;
        int yy = (wy * 8 + (t >> 3) + 4) & 255;
        int xx = (wx * 8 + (t & 7) + 4) & 255;
        const float* xp = x + ((size_t)(b * 192 + c0)) * 65536 + yy * 256 + xx;
        float v0 = xp[0], v1 = xp[65536];
        __nv_bfloat16 h0 = __float2bfloat16(v0), h1 = __float2bfloat16(v1);
        float r0 = v0 - __bfloat162float(h0), r1 = v1 - __bfloat162float(h1);
        int off = t * 400 + c0 * 2;
        *(u32*)(sm + A_HI + off) =
            (u32)__bfloat16_as_ushort(h0) | ((u32)__bfloat16_as_ushort(h1) << 16);
        *(u32*)(sm + A_LO + off) = packbf(r0, r1);
    }
    __syncthreads();

    int g = lane >> 2, tig = lane & 3;
    int mblk = (wid & 3) * 16, nblk = (wid >> 2) * 32;
    const uint4* wfh = (const uint4*)g_wQf;
    const uint4* wfl = (const uint4*)(g_wQf + 55296);

    #pragma unroll 1
    for (int nc = 0; nc < 9; nc++) {
        float cc[4][4];
        #pragma unroll
        for (int nt = 0; nt < 4; nt++)
            #pragma unroll
            for (int q = 0; q < 4; q++) cc[nt][q] = 0.f;

        gemm_chunk(smb, lane, wid, wfh, wfl, nc, cc);

        // epilogue: +bias, write [t][o] rows
        int row0 = mblk + g;
        #pragma unroll
        for (int nt = 0; nt < 4; nt++) {
            int o = nc * 64 + nblk + nt * 8 + tig * 2;
            float2 bo = *(const float2*)&qkv_b[o];
            size_t base = (size_t)(win * 64 + row0) * QROW + o;
            *(float2*)&g_qkv[base] =
                make_float2(cc[nt][0] + bo.x, cc[nt][1] + bo.y);
            *(float2*)&g_qkv[base + 8 * QROW] =
                make_float2(cc[nt][2] + bo.x, cc[nt][3] + bo.y);
        }
    }
}

// ---------------- kernel 2: windowed attention (fp32, verified) ----------------
__global__ __launch_bounds__(64) void attn_kernel(const float* __restrict__ rpb_table) {
    __shared__ float Ks[NTOK][32];
    __shared__ float Vs[NTOK][32];
    __shared__ float rpbs[225];
    __shared__ int   regsh[NTOK];

    int win = blockIdx.x, h = blockIdx.y;
    int wy = (win >> 5) & 31, wx = win & 31;
    int i = threadIdx.x;

    const float* base = g_qkv + (size_t)win * (NTOK * QROW);
    {
        const float4* krow = (const float4*)(base + (size_t)i * QROW + 192 + h * 32);
        const float4* vrow = (const float4*)(base + (size_t)i * QROW + 384 + h * 32);
        #pragma unroll
        for (int m = 0; m < 8; m++) {
            ((float4*)Ks[i])[m] = krow[m];
            ((float4*)Vs[i])[m] = vrow[m];
        }
    }
    for (int idx = i; idx < 225; idx += 64) rpbs[idx] = rpb_table[idx * HEADS + h];
    {
        int iy = i >> 3, ix = i & 7;
        int yt = wy * 8 + iy, xt = wx * 8 + ix;
        int ry = (yt < 248) ? 0 : ((yt < 252) ? 1 : 2);
        int rx = (xt < 248) ? 0 : ((xt < 252) ? 1 : 2);
        regsh[i] = ry * 3 + rx;
    }

    u64 q2[16];
    {
        const ulonglong2* qp = (const ulonglong2*)(base + (size_t)i * QROW + h * 32);
        #pragma unroll
        for (int m = 0; m < 8; m++) {
            ulonglong2 v = qp[m];
            q2[2 * m] = v.x; q2[2 * m + 1] = v.y;
        }
    }
    __syncthreads();

    int iy = i >> 3, ix = i & 7;
    int regi = regsh[i];
    int rb = (iy + 7) * 15 + (ix + 7);

    float l = 0.f;
    u64 acc2[16];
    #pragma unroll
    for (int dp = 0; dp < 16; dp++) acc2[dp] = 0ull;

    #pragma unroll 2
    for (int j = 0; j < NTOK; j++) {
        const ulonglong2* kp = (const ulonglong2*)Ks[j];
        u64 s2 = 0ull;
        #pragma unroll
        for (int m = 0; m < 8; m++) {
            ulonglong2 kv = kp[m];
            ffma2(s2, q2[2 * m], kv.x);
            ffma2(s2, q2[2 * m + 1], kv.y);
        }
        float2 sp = unpack2(s2);
        float s = sp.x + sp.y;
        float bias = rpbs[rb - (j >> 3) * 15 - (j & 7)];
        float msk  = (regi != regsh[j]) ? -100.f : 0.f;
        float e = __expf(fmaf(s, SCALE, bias + msk));
        l += e;
        u64 es = splat2(e);
        const ulonglong2* vp = (const ulonglong2*)Vs[j];
        #pragma unroll
        for (int m = 0; m < 8; m++) {
            ulonglong2 vv = vp[m];
            ffma2(acc2[2 * m], es, vv.x);
            ffma2(acc2[2 * m + 1], es, vv.y);
        }
    }

    // epilogue: normalize, hi/lo split, write bf16x2 rows [row][96 u32]
    float invl = 1.f / l;
    u32 hiw[16], low[16];
    #pragma unroll
    for (int dp = 0; dp < 16; dp++) {
        float2 v = unpack2(acc2[dp]);
        v.x *= invl; v.y *= invl;
        __nv_bfloat16 h0 = __float2bfloat16(v.x), h1 = __float2bfloat16(v.y);
        hiw[dp] = (u32)__bfloat16_as_ushort(h0) | ((u32)__bfloat16_as_ushort(h1) << 16);
        low[dp] = packbf(v.x - __bfloat162float(h0), v.y - __bfloat162float(h1));
    }
    size_t rbase = (size_t)(win * 64 + i) * 96 + h * 16;
    #pragma unroll
    for (int m = 0; m < 4; m++) {
        *(uint4*)&g_oAh[rbase + m * 4] =
            make_uint4(hiw[4 * m], hiw[4 * m + 1], hiw[4 * m + 2], hiw[4 * m + 3]);
        *(uint4*)&g_oAl[rbase + m * 4] =
            make_uint4(low[4 * m], low[4 * m + 1], low[4 * m + 2], low[4 * m + 3]);
    }
}

// ---------------- kernel 3: proj GEMM + reverse-shift scatter ------------------
__global__ __launch_bounds__(256, 3) void proj_kernel(const float* __restrict__ proj_b,
                                                      float* __restrict__ out) {
    extern __shared__ __align__(16) char sm[];
    u32 smb = smem_u32(sm);
    int tid = threadIdx.x, lane = tid & 31, wid = tid >> 5;
    int win = blockIdx.x;
    int b = win >> 10, wy = (win >> 5) & 31, wx = win & 31;

    // stage A: copy pre-split attn output rows (stride 192 -> 200 halves)
    for (int i = tid; i < 1536; i += 256) {
        int row = i / 24, seg = i % 24;
        int off = row * 400 + seg * 16;
        *(uint4*)(sm + A_HI + off) =
            ((const uint4*)g_oAh)[(size_t)(win * 64 + row) * 24 + seg];
        *(uint4*)(sm + A_LO + off) =
            ((const uint4*)g_oAl)[(size_t)(win * 64 + row) * 24 + seg];
    }
    __syncthreads();

    int g = lane >> 2, tig = lane & 3;
    int mblk = (wid & 3) * 16, nblk = (wid >> 2) * 32;
    const uint4* wfh = (const uint4*)g_wPf;
    const uint4* wfl = (const uint4*)(g_wPf + 18432);

    #pragma unroll 1
    for (int nc = 0; nc < 3; nc++) {
        float cc[4][4];
        #pragma unroll
        for (int nt = 0; nt < 4; nt++)
            #pragma unroll
            for (int q = 0; q < 4; q++) cc[nt][q] = 0.f;

        gemm_chunk(smb, lane, wid, wfh, wfl, nc, cc);

        // epilogue: +bias, reverse-shift NCHW scatter
        int row0 = mblk + g;          // token t of this window
        int t1 = row0 + 8;
        int yy0 = (wy * 8 + (row0 >> 3) + 4) & 255;
        int yy1 = (wy * 8 + (t1 >> 3) + 4) & 255;
        int xx  = (wx * 8 + (row0 & 7) + 4) & 255;
        size_t p0 = (size_t)yy0 * 256 + xx;
        size_t p1 = (size_t)yy1 * 256 + xx;
        #pragma unroll
        for (int nt = 0; nt < 4; nt++) {
            int o = nc * 64 + nblk + nt * 8 + tig * 2;
            float2 bo = *(const float2*)&proj_b[o];
            size_t c0 = (size_t)(b * 192 + o) * 65536;
            size_t c1 = c0 + 65536;
            out[c0 + p0] = cc[nt][0] + bo.x;
            out[c1 + p0] = cc[nt][1] + bo.y;
            out[c0 + p1] = cc[nt][2] + bo.x;
            out[c1 + p1] = cc[nt][3] + bo.y;
        }
    }
}

// ---------------- launch --------------------------------------------------------
extern "C" void kernel_launch(void* const* d_in, const int* in_sizes, int n_in,
                              void* d_out, int out_size) {
    const float* x      = (const float*)d_in[0];
    const float* qkv_w  = (const float*)d_in[1];
    const float* qkv_b  = (const float*)d_in[2];
    const float* proj_w = (const float*)d_in[3];
    const float* proj_b = (const float*)d_in[4];
    const float* rpb    = (const float*)d_in[5];
    float* out = (float*)d_out;

    cudaFuncSetAttribute(qkv_kernel, cudaFuncAttributeMaxDynamicSharedMemorySize, SMEM_SZ);
    cudaFuncSetAttribute(proj_kernel, cudaFuncAttributeMaxDynamicSharedMemorySize, SMEM_SZ);

    prep_frag<<<216, 256>>>(qkv_w, proj_w);
    qkv_kernel<<<4096, 256, SMEM_SZ>>>(x, qkv_b);
    attn_kernel<<<dim3(4096, HEADS), 64>>>(rpb);
    proj_kernel<<<4096, 256, SMEM_SZ>>>(proj_b, out);
}